// round 4
// baseline (speedup 1.0000x reference)
#include <cuda_runtime.h>

// Spherical: out = x * |s| — pure HBM stream (268 MB).
// R4: software-pipelined blocks — loads of chunk j+1 issued before stores of
//     chunk j, so the memory pipe never drains during store retirement.

#define THREADS 256
#define V 4            // float4 per thread per iteration
#define ITERS 4        // iterations per block
#define CHUNK (THREADS * V)          // 1024 float4 per iteration
#define BLOCK_SPAN (CHUNK * ITERS)   // 4096 float4 per block

__global__ void __launch_bounds__(THREADS) spherical_scale_kernel(
    const float4* __restrict__ x,
    const float* __restrict__ s,
    float4* __restrict__ out)
{
    const float scale = fabsf(__ldg(s));

    const int base = blockIdx.x * BLOCK_SPAN + threadIdx.x;
    const float4* __restrict__ xp = x + base;
    float4* __restrict__ op = out + base;

    // Prologue: loads for chunk 0 (4 independent LDG.128).
    float4 a0 = __ldcs(xp + 0 * THREADS);
    float4 a1 = __ldcs(xp + 1 * THREADS);
    float4 a2 = __ldcs(xp + 2 * THREADS);
    float4 a3 = __ldcs(xp + 3 * THREADS);

    #pragma unroll
    for (int j = 0; j < ITERS - 1; j++) {
        // Issue next chunk's loads BEFORE storing current chunk.
        const float4* xn = xp + (j + 1) * CHUNK;
        float4 b0 = __ldcs(xn + 0 * THREADS);
        float4 b1 = __ldcs(xn + 1 * THREADS);
        float4 b2 = __ldcs(xn + 2 * THREADS);
        float4 b3 = __ldcs(xn + 3 * THREADS);

        a0.x *= scale; a0.y *= scale; a0.z *= scale; a0.w *= scale;
        a1.x *= scale; a1.y *= scale; a1.z *= scale; a1.w *= scale;
        a2.x *= scale; a2.y *= scale; a2.z *= scale; a2.w *= scale;
        a3.x *= scale; a3.y *= scale; a3.z *= scale; a3.w *= scale;

        float4* on = op + j * CHUNK;
        __stcs(on + 0 * THREADS, a0);
        __stcs(on + 1 * THREADS, a1);
        __stcs(on + 2 * THREADS, a2);
        __stcs(on + 3 * THREADS, a3);

        a0 = b0; a1 = b1; a2 = b2; a3 = b3;
    }

    // Epilogue: store last chunk.
    a0.x *= scale; a0.y *= scale; a0.z *= scale; a0.w *= scale;
    a1.x *= scale; a1.y *= scale; a1.z *= scale; a1.w *= scale;
    a2.x *= scale; a2.y *= scale; a2.z *= scale; a2.w *= scale;
    a3.x *= scale; a3.y *= scale; a3.z *= scale; a3.w *= scale;

    float4* on = op + (ITERS - 1) * CHUNK;
    __stcs(on + 0 * THREADS, a0);
    __stcs(on + 1 * THREADS, a1);
    __stcs(on + 2 * THREADS, a2);
    __stcs(on + 3 * THREADS, a3);
}

// Generic scalar fallback for remainder (unused at 8192x4096).
__global__ void __launch_bounds__(256) spherical_scale_tail(
    const float* __restrict__ x,
    const float* __restrict__ s,
    float* __restrict__ out,
    int start, int n)
{
    const float scale = fabsf(__ldg(s));
    int i = start + blockIdx.x * blockDim.x + threadIdx.x;
    if (i < n) out[i] = x[i] * scale;
}

extern "C" void kernel_launch(void* const* d_in, const int* in_sizes, int n_in,
                              void* d_out, int out_size)
{
    const float4* x = (const float4*)d_in[0];
    const float*  s = (const float*)d_in[1];
    float4* out = (float4*)d_out;

    const int n  = in_sizes[0];            // 33554432
    const int n4 = n / 4;                  // 8388608
    const int blocks = n4 / BLOCK_SPAN;    // 2048 (exact)

    spherical_scale_kernel<<<blocks, THREADS>>>(x, s, out);

    const int covered = blocks * BLOCK_SPAN * 4;
    if (covered < n) {
        const int rem = n - covered;
        spherical_scale_tail<<<(rem + 255) / 256, 256>>>(
            (const float*)d_in[0], s, (float*)d_out, covered, n);
    }
}

// round 5
// speedup vs baseline: 1.0360x; 1.0360x over previous
#include <cuda_runtime.h>

// Spherical: out = x * |s| — pure HBM stream (268 MB).
// R5: 256-bit vector ld/st (v8.f32, sm_100+-family) — halves LSU instruction
//     count and packs 8 lines per L1tex wavefront-group. Layout mirrors the
//     best-measured R2 config (64B/thread, 8192 blocks x 256 threads).

#define THREADS 256

__device__ __forceinline__ void ld_v8_cs(const float* p, float* v) {
    asm volatile(
        "ld.global.cs.v8.f32 {%0,%1,%2,%3,%4,%5,%6,%7}, [%8];"
        : "=f"(v[0]), "=f"(v[1]), "=f"(v[2]), "=f"(v[3]),
          "=f"(v[4]), "=f"(v[5]), "=f"(v[6]), "=f"(v[7])
        : "l"(p));
}

__device__ __forceinline__ void st_v8_cs(float* p, const float* v) {
    asm volatile(
        "st.global.cs.v8.f32 [%0], {%1,%2,%3,%4,%5,%6,%7,%8};"
        :: "l"(p),
           "f"(v[0]), "f"(v[1]), "f"(v[2]), "f"(v[3]),
           "f"(v[4]), "f"(v[5]), "f"(v[6]), "f"(v[7])
        : "memory");
}

__global__ void __launch_bounds__(THREADS) spherical_scale_kernel(
    const float* __restrict__ x,
    const float* __restrict__ s,
    float* __restrict__ out)
{
    const float scale = fabsf(__ldg(s));

    // Block covers 512 v8-chunks (= 4096 floats... no: 512*8 = 4096 floats).
    // Thread t handles v8 indices blockIdx*512 + t and + 256 (coalesced).
    const long long c0 = (long long)blockIdx.x * (THREADS * 2) + threadIdx.x;
    const long long c1 = c0 + THREADS;

    float a[8], b[8];
    ld_v8_cs(x + c0 * 8, a);   // two independent 256-bit loads in flight
    ld_v8_cs(x + c1 * 8, b);

    #pragma unroll
    for (int k = 0; k < 8; k++) a[k] *= scale;
    #pragma unroll
    for (int k = 0; k < 8; k++) b[k] *= scale;

    st_v8_cs(out + c0 * 8, a);
    st_v8_cs(out + c1 * 8, b);
}

// Generic scalar fallback for remainder (unused at 8192x4096).
__global__ void __launch_bounds__(256) spherical_scale_tail(
    const float* __restrict__ x,
    const float* __restrict__ s,
    float* __restrict__ out,
    int start, int n)
{
    const float scale = fabsf(__ldg(s));
    int i = start + blockIdx.x * blockDim.x + threadIdx.x;
    if (i < n) out[i] = x[i] * scale;
}

extern "C" void kernel_launch(void* const* d_in, const int* in_sizes, int n_in,
                              void* d_out, int out_size)
{
    const float* x = (const float*)d_in[0];
    const float* s = (const float*)d_in[1];
    float* out = (float*)d_out;

    const int n = in_sizes[0];                 // 33554432
    const int floats_per_block = THREADS * 16; // 4096
    const int blocks = n / floats_per_block;   // 8192 (exact)

    spherical_scale_kernel<<<blocks, THREADS>>>(x, s, out);

    const int covered = blocks * floats_per_block;
    if (covered < n) {
        const int rem = n - covered;
        spherical_scale_tail<<<(rem + 255) / 256, 256>>>(x, s, out, covered, n);
    }
}